// round 17
// baseline (speedup 1.0000x reference)
#include <cuda_runtime.h>
#include <math.h>
#include <stdint.h>

// Problem constants
#define NB 128   // batch
#define TS 512   // timesteps
#define DI 512   // input dim
#define HD 512   // hidden dim

#define KSTEPS 32           // recurrence steps per kernel launch
#define NKERN  (TS / KSTEPS)

typedef unsigned long long ull;

// inter-CTA step flags: [group y][producer x], monotonic step values.
// Zeroed by flag_reset each replay (keeps graph replays deterministic).
__device__ __align__(16) unsigned g_flags[16 * 8];

// ---------------- packed f32x2 helpers (sm_100+ FFMA2 path) ----------------
__device__ __forceinline__ void fma2(ull& acc, ull a, ull b) {
    asm("fma.rn.f32x2 %0, %1, %2, %0;" : "+l"(acc) : "l"(a), "l"(b));
}
__device__ __forceinline__ void add2(ull& a, ull b) {
    asm("add.rn.f32x2 %0, %0, %1;" : "+l"(a) : "l"(b));
}
__device__ __forceinline__ void unpack2(ull v, float& lo, float& hi) {
    unsigned int a, b;
    asm("mov.b64 {%0, %1}, %2;" : "=r"(a), "=r"(b) : "l"(v));
    lo = __uint_as_float(a);
    hi = __uint_as_float(b);
}
__device__ __forceinline__ ull pack_dup(uint32_t h) {
    ull r;
    asm("mov.b64 %0, {%1, %1};" : "=l"(r) : "r"(h));
    return r;
}

__device__ __forceinline__ uint32_t smem_u32(const void* p) {
    uint32_t a;
    asm("{ .reg .u64 t; cvta.to.shared.u64 t, %1; cvt.u32.u64 %0, t; }"
        : "=r"(a) : "l"(p));
    return a;
}

// ---------------- cp.async + mbarrier ----------------
__device__ __forceinline__ void cp_async16(uint32_t dst, const void* src) {
    asm volatile("cp.async.cg.shared.global [%0], [%1], 16;"
                 :: "r"(dst), "l"(src) : "memory");
}
__device__ __forceinline__ void cp_async_arrive(uint32_t mbar) {
    asm volatile("cp.async.mbarrier.arrive.noinc.shared.b64 [%0];"
                 :: "r"(mbar) : "memory");
}
__device__ __forceinline__ void mbar_init(uint32_t mbar, uint32_t cnt) {
    asm volatile("mbarrier.init.shared.b64 [%0], %1;"
                 :: "r"(mbar), "r"(cnt) : "memory");
}
__device__ __forceinline__ void mbar_wait0(uint32_t mbar) {
    asm volatile(
        "{\n\t.reg .pred P;\n\t"
        "W%=:\n\t"
        "mbarrier.try_wait.parity.shared.b64 P, [%0], 0;\n\t"
        "@!P bra W%=;\n\t}"
        :: "r"(mbar) : "memory");
}

// ---------------- PDL ----------------
__device__ __forceinline__ void pdl_wait() {
    asm volatile("griddepcontrol.wait;" ::: "memory");
}
__device__ __forceinline__ void pdl_trigger() {
    asm volatile("griddepcontrol.launch_dependents;" ::: "memory");
}

// ---------------- L2 flag ops ----------------
__device__ __forceinline__ void st_rel_u32(unsigned* p, unsigned v) {
    asm volatile("st.release.gpu.global.u32 [%0], %1;"
                 :: "l"(p), "r"(v) : "memory");
}
__device__ __forceinline__ ull ld_acq_u64(const ull* p) {
    ull v;
    asm volatile("ld.acquire.gpu.global.u64 %0, [%1];"
                 : "=l"(v) : "l"(p) : "memory");
    return v;
}
// wait until all 8 producer flags of group y reach >= want
__device__ __forceinline__ void spin_group(int y, unsigned want) {
    const ull* fp = (const ull*)(g_flags + y * 8);
    for (;;) {
        bool ok = true;
#pragma unroll
        for (int i = 0; i < 4; i++) {
            ull v = ld_acq_u64(fp + i);
            unsigned lo = (unsigned)v, hi = (unsigned)(v >> 32);
            ok &= (lo >= want) & (hi >= want);
        }
        if (ok) return;
        asm volatile("nanosleep.u32 64;");
    }
}

__global__ void flag_reset() {
    if (threadIdx.x < 128) g_flags[threadIdx.x] = 0;
}

// ---------------------------------------------------------------------------
// Kernel 1: xW = x @ Wx + b  (unchanged — proven, rel_err 3.7e-7)
// ---------------------------------------------------------------------------
__global__ __launch_bounds__(256) void xw_gemm(
    const float* __restrict__ A,
    const float* __restrict__ B,
    const float* __restrict__ bias,
    float* __restrict__ C)
{
    __shared__ float2 As2[128][16];
    __shared__ float  Bs[16][128];

    const int m0  = blockIdx.y * 128;
    const int n0  = blockIdx.x * 128;
    const int tid = threadIdx.x;
    const int tn  = tid & 15;
    const int tm  = tid >> 4;

    ull acc[8][4];
#pragma unroll
    for (int i = 0; i < 8; i++)
#pragma unroll
        for (int j = 0; j < 4; j++) acc[i][j] = 0ULL;

    for (int k0 = 0; k0 < DI; k0 += 16) {
#pragma unroll
        for (int j = 0; j < 2; j++) {
            int f  = tid + j * 256;
            int m  = f >> 2;
            int kq = f & 3;
            float4 v = *(const float4*)(A + (size_t)(m0 + m) * DI + k0 + kq * 4);
            *(float4*)(&As2[m][kq * 4])     = make_float4(v.x, v.x, v.y, v.y);
            *(float4*)(&As2[m][kq * 4 + 2]) = make_float4(v.z, v.z, v.w, v.w);
        }
#pragma unroll
        for (int j = 0; j < 2; j++) {
            int f  = tid + j * 256;
            int k  = f >> 5;
            int nq = f & 31;
            *(float4*)(&Bs[k][nq * 4]) =
                *(const float4*)(B + (size_t)(k0 + k) * HD + n0 + nq * 4);
        }
        __syncthreads();

#pragma unroll
        for (int k = 0; k < 16; k++) {
            ulonglong2 b01 = *(const ulonglong2*)(&Bs[k][tn * 8]);
            ulonglong2 b23 = *(const ulonglong2*)(&Bs[k][tn * 8 + 4]);
#pragma unroll
            for (int i = 0; i < 8; i++) {
                ull a = *(const ull*)(&As2[tm * 8 + i][k]);
                fma2(acc[i][0], a, b01.x);
                fma2(acc[i][1], a, b01.y);
                fma2(acc[i][2], a, b23.x);
                fma2(acc[i][3], a, b23.y);
            }
        }
        __syncthreads();
    }

    const float4 bb0 = *(const float4*)(bias + n0 + tn * 8);
    const float4 bb1 = *(const float4*)(bias + n0 + tn * 8 + 4);
#pragma unroll
    for (int i = 0; i < 8; i++) {
        float r0, r1, r2, r3, r4, r5, r6, r7;
        unpack2(acc[i][0], r0, r1);
        unpack2(acc[i][1], r2, r3);
        unpack2(acc[i][2], r4, r5);
        unpack2(acc[i][3], r6, r7);
        float* p = C + (size_t)(m0 + tm * 8 + i) * HD + n0 + tn * 8;
        *(float4*)p       = make_float4(r0 + bb0.x, r1 + bb0.y, r2 + bb0.z, r3 + bb0.w);
        *(float4*)(p + 4) = make_float4(r4 + bb1.x, r5 + bb1.y, r6 + bb1.z, r7 + bb1.w);
    }
}

// ---------------------------------------------------------------------------
// Kernel 2: KSTEPS recurrence steps per launch, L2-flag group handshake.
//
// Grid (8,16) = 128 CTAs <= 148 SMs, 1 CTA/SM -> single wave, all co-resident
// (spin-wait deadlock-free). CTA (x,y): rows [8y,8y+8), cols [64x,64x+64).
//
// Wh slice cp.async'd ONCE per kernel (4 chunk mbarriers), issued before
// pdl_wait so it overlaps the previous kernel. Compute core = R12/R15 proven:
// oct-major Ws (LDS.128 4-phase), k-swizzled Hs (LDS.32 1-phase), 8x8 FFMA2
// register block, smem tree reduce, xw + tanhf epilogue.
//
// Step sync (internal, s>=1): producers stored flag value t via st.release
// after __syncthreads (cumulative -> orders all threads' h stores); consumer
// thread-0 spins ld.acquire.u64 until all 8 group flags >= t, then
// __syncthreads broadcasts visibility. Monotonic >= compare is safe against
// producer overshoot; flags are zeroed per replay by flag_reset.
// Step 0 needs no flags: ordering comes from the PDL chain.
// ---------------------------------------------------------------------------
#define WOCT    16400
#define WS_OFF  0
#define HS_OFF  131200                    // 8 oct regions
#define HR      2576
#define RED_OFF (HS_OFF + 8 * HR)         // 151808
#define MB_OFF  (RED_OFF + 256 * 272)     // 221440
#define STEP_SMEM (MB_OFF + 64)           // 221504

__global__ __launch_bounds__(256, 1)
void rnn_steps(const float* __restrict__ Wh,
               const float* __restrict__ h0,
               float* __restrict__ out,
               int t0)
{
    extern __shared__ char smem[];
    const uint32_t sb = smem_u32(smem);
    const int tid = threadIdx.x;
    const int bx  = blockIdx.x;           // col group 0..7
    const int by  = blockIdx.y;           // row group 0..15
    const int m0  = by * 8;
    const int n0  = bx * 64;

    // mbarriers for the 4 Wh chunks (fresh each launch -> parity 0)
    if (tid == 0) {
#pragma unroll
        for (int c = 0; c < 4; c++) mbar_init(sb + MB_OFF + 8 * c, 256);
    }
    __syncthreads();

    // ---- stream Wh slice once: 4 chunks x 8 float4/thread (pre-PDL) ----
#pragma unroll
    for (int c = 0; c < 4; c++) {
#pragma unroll
        for (int j = 0; j < 8; j++) {
            int f   = tid + (c * 8 + j) * 256;
            int k   = f >> 4;
            int nq  = f & 15;
            int oct = nq >> 1;
            int hf  = nq & 1;
            cp_async16(sb + WS_OFF + oct * WOCT + k * 32 + hf * 16,
                       Wh + (size_t)k * HD + n0 + nq * 4);
        }
        cp_async_arrive(sb + MB_OFF + 8 * c);
    }

    // wait for the previous kernel in the PDL chain (h_{t0-1} / xw visible)
    pdl_wait();

    const int ksl = tid >> 3;              // 0..31, k in [16ksl, 16ksl+16)
    const int grp = tid & 7;               // col oct
    const int er  = tid >> 5;              // epilogue row
    const int ecp = tid & 31;              // epilogue colpair

    const char* hb = smem + HS_OFF + ksl * 80;
    const char* wb = smem + WS_OFF + (size_t)grp * WOCT + ksl * 512;
    char* pstore   = smem + RED_OFF + (grp * 4) * 272 + ksl * 8;

    for (int s = 0; s < KSTEPS; s++) {
        const int t = t0 + s;

        if (s > 0) {
            if (tid == 0) spin_group(by, (unsigned)t);
            __syncthreads();               // broadcast acquire to the block
        }

        // ---- stage h_{t-1} into swizzled Hs: 4 float4/thread ----
        const float* hg;
        size_t hstr;
        if (t == 0) { hg = h0; hstr = HD; }
        else        { hg = out + (size_t)(t - 1) * HD; hstr = (size_t)TS * HD; }
#pragma unroll
        for (int j = 0; j < 4; j++) {
            int f   = tid + j * 256;
            int row = f >> 7;
            int q   = f & 127;             // float4 index; k = 4q
            *(float4*)(smem + HS_OFF + row * HR + q * 16 + (q >> 2) * 16) =
                *(const float4*)(hg + (size_t)(m0 + row) * hstr + q * 4);
        }

        // xw prefetch for this thread's output slot
        float* pio = out + ((size_t)(m0 + er) * TS + t) * HD + n0 + ecp * 2;
        float2 xw = *(const float2*)pio;
        __syncthreads();

        if (s == 0) mbar_wait0(sb + MB_OFF + 8 * (ksl >> 3));

        // ---- 8x8 register-blocked partial GEMM over 16 k ----
        ull acc[8][4];
#pragma unroll
        for (int r = 0; r < 8; r++)
#pragma unroll
            for (int j = 0; j < 4; j++) acc[r][j] = 0ULL;

#pragma unroll 8
        for (int kk = 0; kk < 16; kk++) {
            ull hp[8];
#pragma unroll
            for (int r = 0; r < 8; r++)
                hp[r] = pack_dup(*(const uint32_t*)(hb + r * HR + kk * 4));
            ulonglong2 wA = *(const ulonglong2*)(wb + kk * 32);
            ulonglong2 wB = *(const ulonglong2*)(wb + kk * 32 + 16);
#pragma unroll
            for (int r = 0; r < 8; r++) {
                fma2(acc[r][0], hp[r], wA.x);
                fma2(acc[r][1], hp[r], wA.y);
                fma2(acc[r][2], hp[r], wB.x);
                fma2(acc[r][3], hp[r], wB.y);
            }
        }

        // ---- dump 32 partials ----
#pragma unroll
        for (int r = 0; r < 8; r++)
#pragma unroll
            for (int j = 0; j < 4; j++)
                *(ull*)(pstore + (size_t)r * 32 * 272 + j * 272) = acc[r][j];
        __syncthreads();

        // ---- tree reduce + epilogue ----
        {
            const char* rb = smem + RED_OFF + tid * 272;
            ulonglong2 v[16];
#pragma unroll
            for (int q = 0; q < 16; q++)
                v[q] = *(const ulonglong2*)(rb + q * 16);
            ull sm[8];
#pragma unroll
            for (int q = 0; q < 8; q++) {
                ull a = v[2 * q].x;
                add2(a, v[2 * q].y);
                ull b = v[2 * q + 1].x;
                add2(b, v[2 * q + 1].y);
                add2(a, b);
                sm[q] = a;
            }
            add2(sm[0], sm[1]); add2(sm[2], sm[3]);
            add2(sm[4], sm[5]); add2(sm[6], sm[7]);
            add2(sm[0], sm[2]); add2(sm[4], sm[6]);
            add2(sm[0], sm[4]);

            float slo, shi;
            unpack2(sm[0], slo, shi);
            float2 hv;
            hv.x = tanhf(xw.x + slo);
            hv.y = tanhf(xw.y + shi);
            *(float2*)pio = hv;            // h_t (also the output)
        }

        // ---- publish h_t to the group (not needed after the last step) ----
        if (s < KSTEPS - 1) {
            __syncthreads();               // all h stores done (cumulative)
            if (tid == 0) st_rel_u32(&g_flags[by * 8 + bx], (unsigned)(t + 1));
        }
    }

    // let the next 32-step kernel launch + run its Wh prologue
    pdl_trigger();
}

// ---------------------------------------------------------------------------
// Launch: flag reset, xW, then NKERN PDL-chained 32-step kernels.
// ---------------------------------------------------------------------------
extern "C" void kernel_launch(void* const* d_in, const int* in_sizes, int n_in,
                              void* d_out, int out_size) {
    (void)in_sizes; (void)n_in; (void)out_size;
    const float* x  = (const float*)d_in[0];   // [128, 512, 512]
    const float* h0 = (const float*)d_in[1];   // [128, 512]
    const float* Wx = (const float*)d_in[2];   // [512, 512]
    const float* Wh = (const float*)d_in[3];   // [512, 512]
    const float* b  = (const float*)d_in[4];   // [512]
    float* out = (float*)d_out;                // [128, 512, 512]

    flag_reset<<<1, 128>>>();

    dim3 gx(HD / 128, (NB * TS) / 128);        // (4, 512)
    xw_gemm<<<gx, 256>>>(x, Wx, b, out);

    cudaFuncSetAttribute(rnn_steps,
                         cudaFuncAttributeMaxDynamicSharedMemorySize,
                         STEP_SMEM);

    cudaLaunchAttribute at[1];
    at[0].id = cudaLaunchAttributeProgrammaticStreamSerialization;
    at[0].val.programmaticStreamSerializationAllowed = 1;

    for (int k = 0; k < NKERN; k++) {
        cudaLaunchConfig_t cfg = {};
        cfg.gridDim          = dim3(8, 16, 1);
        cfg.blockDim         = dim3(256, 1, 1);
        cfg.dynamicSmemBytes = STEP_SMEM;
        cfg.stream           = 0;
        cfg.attrs            = at;
        cfg.numAttrs         = 1;

        cudaError_t e = cudaLaunchKernelEx(&cfg, rnn_steps,
                                           Wh, h0, out, k * KSTEPS);
        if (e != cudaSuccess) {
            // PDL attr rejected: plain launch (griddepcontrol ops no-op)
            rnn_steps<<<dim3(8, 16), 256, STEP_SMEM>>>(Wh, h0, out, k * KSTEPS);
        }
    }
}